// round 2
// baseline (speedup 1.0000x reference)
#include <cuda_runtime.h>
#include <cuda_bf16.h>
#include <cstdint>

#define Bn 256
#define Sn 2048
#define Tn 32
#define FULLMASK 0xffffffffu
#define LOG32F 3.4657359027997265f

// Scratch (device globals are the sanctioned scratch mechanism)
__device__ unsigned char g_hist[(size_t)Bn * (Sn - 1) * Tn];  // backpointers, 16.8 MB
__device__ float g_den[Bn];
__device__ float g_num[Bn];
__device__ int   g_last[Bn];

// ---------------------------------------------------------------------------
// Main kernel: 768 single-warp CTAs.
//   role 0 (blocks   0..255): forward algorithm (linear domain) -> g_den[b]
//   role 1 (blocks 256..511): viterbi (bit-exact)               -> g_hist, g_last[b]
//   role 2 (blocks 512..767): numerator                         -> g_num[b]
// ---------------------------------------------------------------------------
__global__ __launch_bounds__(32)
void crf_main_kernel(const float* __restrict__ pred,
                     const int*   __restrict__ amask,
                     const int*   __restrict__ labels,
                     const float* __restrict__ startv,
                     const float* __restrict__ endv,
                     const float* __restrict__ trans)
{
    const int role = blockIdx.x >> 8;
    const int b    = blockIdx.x & 255;
    const int j    = threadIdx.x;

    const float* em = pred + (size_t)b * Sn * Tn;

    __shared__ __align__(16) float buf[2][32];
    __shared__ signed char mk[Sn];

    if (role < 2) {
        const int* am = amask + (size_t)b * Sn;
        for (int t = j; t < Sn; t += 32) mk[t] = (signed char)am[t];
        __syncwarp();
    }

    if (role == 0) {
        // ------- Forward algorithm in linear domain with deferred renorm ---
        // State: s_j = exp(f_j - C). Matrix folded: tc_ij = exp(trans_ij)/32,
        // so each masked step adds log32 to C. Renorm every 16 steps keeps
        // |log s| < ~40 (fp32 exp headroom is 88).
        float tc[32];
        #pragma unroll
        for (int i = 0; i < 32; ++i)
            tc[i] = __expf(trans[i * Tn + j]) * 0.03125f;

        float s  = __expf(startv[j] + em[j]);
        float Lr = 0.f;
        int   nm = 0;

        float emreg[4];
        #pragma unroll
        for (int p = 0; p < 4; ++p) emreg[p] = em[(size_t)(1 + p) * Tn + j];

        for (int tb = 1; tb < Sn; tb += 4) {
            #pragma unroll
            for (int u = 0; u < 4; ++u) {
                const int t = tb + u;
                if (t >= Sn) break;
                const float ee = __expf(emreg[u]);     // off critical path
                const int tn = t + 4;
                if (tn < Sn) emreg[u] = em[(size_t)tn * Tn + j];

                float* sb = buf[t & 1];
                sb[j] = s;
                __syncwarp();

                float a0 = 0.f, a1 = 0.f, a2 = 0.f, a3 = 0.f;
                #pragma unroll
                for (int k = 0; k < 8; ++k) {
                    const float4 q = *(const float4*)(sb + 4 * k);
                    a0 = fmaf(q.x, tc[4 * k + 0], a0);
                    a1 = fmaf(q.y, tc[4 * k + 1], a1);
                    a2 = fmaf(q.z, tc[4 * k + 2], a2);
                    a3 = fmaf(q.w, tc[4 * k + 3], a3);
                }
                const float ns = ((a0 + a1) + (a2 + a3)) * ee;
                const int  m_  = mk[t];
                s  = m_ ? ns : s;
                nm += m_;

                if ((t & 15) == 15) {                   // renorm, amortized
                    const float r  = __shfl_sync(FULLMASK, s, 0);
                    const float rr = __frcp_rn(r);
                    s *= rr;
                    Lr -= __logf(rr);
                }
            }
        }
        // den_b = nm*log32 + Lr + log( sum_j s_j * exp(end_j) )
        float v = s * __expf(endv[j]);
        #pragma unroll
        for (int off = 16; off; off >>= 1)
            v += __shfl_xor_sync(FULLMASK, v, off);
        if (j == 0) g_den[b] = (float)nm * LOG32F + Lr + __logf(v);

    } else if (role == 1) {
        // ------- Viterbi (bit-exact max via FMNMX tree + equality argmax) --
        float tc[32];
        #pragma unroll
        for (int i = 0; i < 32; ++i) tc[i] = trans[i * Tn + j];

        float v = startv[j] + em[j];
        unsigned char* hb = g_hist + (size_t)b * (Sn - 1) * Tn;

        float emreg[4];
        #pragma unroll
        for (int p = 0; p < 4; ++p) emreg[p] = em[(size_t)(1 + p) * Tn + j];

        for (int tb = 1; tb < Sn; tb += 4) {
            #pragma unroll
            for (int u = 0; u < 4; ++u) {
                const int t = tb + u;
                if (t >= Sn) break;
                const float emt = emreg[u];
                const int tn = t + 4;
                if (tn < Sn) emreg[u] = em[(size_t)tn * Tn + j];

                float* vb = buf[t & 1];
                vb[j] = v;
                __syncwarp();

                float c[32];
                #pragma unroll
                for (int k = 0; k < 8; ++k) {
                    const float4 q = *(const float4*)(vb + 4 * k);
                    c[4 * k + 0] = q.x + tc[4 * k + 0];
                    c[4 * k + 1] = q.y + tc[4 * k + 1];
                    c[4 * k + 2] = q.z + tc[4 * k + 2];
                    c[4 * k + 3] = q.w + tc[4 * k + 3];
                }
                // max tree (order-independent, bit-exact)
                float mA[16];
                #pragma unroll
                for (int i = 0; i < 16; ++i) mA[i] = fmaxf(c[2 * i], c[2 * i + 1]);
                float mB[8];
                #pragma unroll
                for (int i = 0; i < 8; ++i) mB[i] = fmaxf(mA[2 * i], mA[2 * i + 1]);
                float mC[4];
                #pragma unroll
                for (int i = 0; i < 4; ++i) mC[i] = fmaxf(mB[2 * i], mB[2 * i + 1]);
                const float mD0 = fmaxf(mC[0], mC[1]);
                const float mD1 = fmaxf(mC[2], mC[3]);
                const float m   = fmaxf(mD0, mD1);

                // first-occurrence argmax: descending scan, exact equality
                int bi = 0;
                #pragma unroll
                for (int i = 31; i >= 0; --i)
                    bi = (c[i] == m) ? i : bi;

                const float nv = m + emt;
                const int m_   = mk[t];
                const int bp   = m_ ? bi : j;
                v = m_ ? nv : v;
                hb[(size_t)(t - 1) * Tn + j] = (unsigned char)bp;
            }
        }
        // last_tag = argmax_j (v_j + end_j), lowest index on ties
        float bv = v + endv[j];
        int   bidx = j;
        #pragma unroll
        for (int off = 16; off; off >>= 1) {
            const float ov = __shfl_xor_sync(FULLMASK, bv, off);
            const int   oi = __shfl_xor_sync(FULLMASK, bidx, off);
            const bool take = (ov > bv) || (ov == bv && oi < bidx);
            bv   = take ? ov : bv;
            bidx = take ? oi : bidx;
        }
        if (j == 0) g_last[b] = bidx;

    } else {
        // ------- Numerator -------------------------------------------------
        const int* lab = labels + (size_t)b * Sn;
        const int* am  = amask  + (size_t)b * Sn;
        float sum = 0.f;
        int   msum = 0;
        for (int t = j; t < Sn; t += 32) {
            const int mt = am[t];
            msum += mt;
            const int tg = lab[t];
            if (t == 0) {
                sum += startv[tg] + em[tg];
            } else {
                const int tp = lab[t - 1];
                sum += (trans[tp * Tn + tg] + em[(size_t)t * Tn + tg]) * (float)mt;
            }
        }
        #pragma unroll
        for (int off = 16; off; off >>= 1) {
            sum  += __shfl_xor_sync(FULLMASK, sum, off);
            msum += __shfl_xor_sync(FULLMASK, msum, off);
        }
        if (j == 0) {
            const int se = msum - 1;
            const int lt = lab[se];
            g_num[b] = sum + endv[lt];
        }
    }
}

// ---------------------------------------------------------------------------
// Backtrace: one warp per batch; stage 32 backpointer rows (1 KB) in SMEM,
// then lane 0 walks the chain at LDS latency instead of DRAM latency.
// ---------------------------------------------------------------------------
__global__ __launch_bounds__(32)
void crf_backtrace_kernel(float* __restrict__ out)
{
    const int b = blockIdx.x;
    const int lane = threadIdx.x;
    __shared__ __align__(16) unsigned char rows[32 * Tn];
    __shared__ int s_tag;

    const unsigned char* hb = g_hist + (size_t)b * (Sn - 1) * Tn;
    float* ob = out + (size_t)b * Sn;

    if (lane == 0) {
        s_tag = g_last[b];
        ob[Sn - 1] = (float)s_tag;
    }
    __syncwarp();

    int r = Sn - 2;
    while (r >= 0) {
        int c0 = r - 31; if (c0 < 0) c0 = 0;
        const int n = r - c0 + 1;
        const uint32_t* src = (const uint32_t*)(hb + (size_t)c0 * Tn);
        uint32_t* dst = (uint32_t*)rows;
        for (int idx = lane; idx < n * 8; idx += 32) dst[idx] = src[idx];
        __syncwarp();
        if (lane == 0) {
            int tag = s_tag;
            for (int k = n - 1; k >= 0; --k) {
                tag = rows[k * Tn + tag];
                ob[c0 + k] = (float)tag;
            }
            s_tag = tag;
        }
        __syncwarp();
        r = c0 - 1;
    }
}

// ---------------------------------------------------------------------------
// Loss: -mean(num - den)
// ---------------------------------------------------------------------------
__global__ void crf_loss_kernel(float* __restrict__ out)
{
    __shared__ float red[Bn];
    const int t = threadIdx.x;
    red[t] = g_num[t] - g_den[t];
    __syncthreads();
    #pragma unroll
    for (int off = 128; off; off >>= 1) {
        if (t < off) red[t] += red[t + off];
        __syncthreads();
    }
    if (t == 0) out[(size_t)Bn * Sn] = -(red[0] / (float)Bn);
}

extern "C" void kernel_launch(void* const* d_in, const int* in_sizes, int n_in,
                              void* d_out, int out_size)
{
    const float* pred   = (const float*)d_in[0];
    const int*   amask  = (const int*)  d_in[1];
    const int*   labels = (const int*)  d_in[2];
    const float* startv = (const float*)d_in[3];
    const float* endv   = (const float*)d_in[4];
    const float* trans  = (const float*)d_in[5];
    float* out = (float*)d_out;

    crf_main_kernel<<<768, 32>>>(pred, amask, labels, startv, endv, trans);
    crf_backtrace_kernel<<<Bn, 32>>>(out);
    crf_loss_kernel<<<1, Bn>>>(out);
}